// round 12
// baseline (speedup 1.0000x reference)
#include <cuda_runtime.h>
#include <math.h>

#define B_TOTAL  2048
#define N_NEIGH  64
#define IN_DIM   256
#define NH       8
#define HD       32

// Scratch (allocation-free rule: __device__ globals)
__device__ float g_v[IN_DIM * NH];                         // v[in][h]
__device__ float g_s[(size_t)B_TOTAL * NH * IN_DIM];       // s[b][h][in]

// Streaming load: no L1 allocation.
__device__ __forceinline__ float4 ldg_na(const float4* p) {
    float4 v;
    asm volatile("ld.global.nc.L1::no_allocate.v4.f32 {%0,%1,%2,%3}, [%4];"
                 : "=f"(v.x), "=f"(v.y), "=f"(v.z), "=f"(v.w) : "l"(p));
    return v;
}

// ---------------------------------------------------------------------------
// Kernel 0: v[in][h] = sum_d W[in][h*32+d] * W_att[h][d]
// ---------------------------------------------------------------------------
__global__ __launch_bounds__(64, 8)
void k_compute_v(const float* __restrict__ W, const float* __restrict__ Wa, int base) {
    const int idx = base + blockIdx.x * 64 + threadIdx.x;
    const int in  = idx >> 3;
    const int h   = idx & 7;
    const float4* row = reinterpret_cast<const float4*>(W + (size_t)in * (NH * HD) + h * HD);
    const float4* wa4 = reinterpret_cast<const float4*>(Wa) + h * 8;
    float4 w[8];
#pragma unroll
    for (int q = 0; q < 8; q++) w[q] = row[q];
    float acc = 0.f;
#pragma unroll
    for (int q = 0; q < 8; q++) {
        float4 a4 = __ldg(&wa4[q]);
        acc += w[q].x * a4.x + w[q].y * a4.y + w[q].z * a4.z + w[q].w * a4.w;
    }
    g_v[in * NH + h] = acc;
}

// ---------------------------------------------------------------------------
// Stage 1: R11 structure; phase-2 alpha via register+shuffle (off the L1 pipe).
//   e[n][h]   = leaky( (hi[n]+hj[n]) . v[:,h] )
//   alpha     = softmax_n(e)
//   s[h][in]  = sum_n alpha[n][h] * hj[n][in]   -> g_s
// alpha_r layout: flat=8n+h stored at alpha_r[(flat%16)*32 + flat/16].
// Dynamic smem (floats): hj_s[64][256]; e_s[64][8]; alpha_r[512]
// ---------------------------------------------------------------------------
#define S1_SMEM_FLOATS (16384 + 512 + 512)
#define S1_SMEM_BYTES  (S1_SMEM_FLOATS * 4)

__global__ __launch_bounds__(256, 2)
void k_stage1(const float* __restrict__ hi, const float* __restrict__ hj, int b_base) {
    extern __shared__ __align__(16) float smem[];
    float* hj_s    = smem;            // [64][256]
    float* e_s     = smem + 16384;    // [64][8]
    float* alpha_r = smem + 16896;    // [512] shuffle-layout

    const int b    = b_base + blockIdx.x;
    const int t    = threadIdx.x;
    const int w    = t >> 5;
    const int lane = t & 31;

    const float4* hib = reinterpret_cast<const float4*>(hi + (size_t)b * N_NEIGH * IN_DIM);
    const float4* hjb = reinterpret_cast<const float4*>(hj + (size_t)b * N_NEIGH * IN_DIM);
    const float4* vg  = reinterpret_cast<const float4*>(g_v);

#pragma unroll
    for (int pass = 0; pass < 2; pass++) {
        const int co = pass * 32;     // float4 column offset within a row

        // v for this lane's fixed in-set: in = 128*pass + 4*lane + j
        float va[4][8];
#pragma unroll
        for (int j = 0; j < 4; j++) {
            const int ia = 128 * pass + 4 * lane + j;
            float4 p0 = vg[ia * 2], p1 = vg[ia * 2 + 1];
            va[j][0]=p0.x; va[j][1]=p0.y; va[j][2]=p0.z; va[j][3]=p0.w;
            va[j][4]=p1.x; va[j][5]=p1.y; va[j][6]=p1.z; va[j][7]=p1.w;
        }

#pragma unroll
        for (int g = 0; g < 2; g++) {
            // ---- front-batched streaming loads: 8 LDG.128, no L1 allocation ----
            float4 A[4], Bv[4];
#pragma unroll
            for (int r = 0; r < 4; r++)
                A[r]  = ldg_na(&hib[(w * 8 + g * 4 + r) * 64 + co + lane]);
#pragma unroll
            for (int r = 0; r < 4; r++)
                Bv[r] = ldg_na(&hjb[(w * 8 + g * 4 + r) * 64 + co + lane]);

            float X[4][4];
#pragma unroll
            for (int r = 0; r < 4; r++) {
                X[r][0] = A[r].x + Bv[r].x; X[r][1] = A[r].y + Bv[r].y;
                X[r][2] = A[r].z + Bv[r].z; X[r][3] = A[r].w + Bv[r].w;
                reinterpret_cast<float4*>(hj_s + (w * 8 + g * 4 + r) * IN_DIM)[co + lane] = Bv[r];
            }

#pragma unroll
            for (int r = 0; r < 4; r++) {
                const int n = w * 8 + g * 4 + r;
                float acc[8];
#pragma unroll
                for (int h = 0; h < 8; h++) {
                    float s = 0.f;
#pragma unroll
                    for (int j = 0; j < 4; j++) s += X[r][j] * va[j][h];
                    acc[h] = s;
                }
#pragma unroll
                for (int st = 0; st < 3; st++) {
                    const int mask = 1 << st;
#pragma unroll
                    for (int p = 0; p < (4 >> st); p++) {
                        float aa = acc[2 * p], bb = acc[2 * p + 1];
                        float sel   = (lane & mask) ? aa : bb;
                        float other = __shfl_xor_sync(0xffffffffu, sel, mask);
                        acc[p] = (lane & mask) ? (bb + other) : (aa + other);
                    }
                }
                float rsum = acc[0];
                rsum += __shfl_xor_sync(0xffffffffu, rsum, 8);
                rsum += __shfl_xor_sync(0xffffffffu, rsum, 16);
                if (lane < 8) {
                    if (pass == 0) e_s[n * NH + lane] = rsum;
                    else           e_s[n * NH + lane] += rsum;
                }
            }
        }
    }
    __syncthreads();

    // ---- Softmax over n (warp w = head w); write alpha in shuffle layout ----
    {
        float e0 = e_s[lane * NH + w];
        float e1 = e_s[(lane + 32) * NH + w];
        e0 = (e0 >= 0.f) ? e0 : 0.2f * e0;   // leaky_relu(., 0.2)
        e1 = (e1 >= 0.f) ? e1 : 0.2f * e1;
        float m = fmaxf(e0, e1);
#pragma unroll
        for (int o = 16; o > 0; o >>= 1)
            m = fmaxf(m, __shfl_xor_sync(0xffffffffu, m, o));
        float p0 = __expf(e0 - m);
        float p1 = __expf(e1 - m);
        float sm = p0 + p1;
#pragma unroll
        for (int o = 16; o > 0; o >>= 1)
            sm += __shfl_xor_sync(0xffffffffu, sm, o);
        float inv = 1.f / sm;
        // flat = 8n + h, h = w. n = lane   -> row j = 8*(lane&1)+w, col lane>>1
        //                       n = lane+32-> same j, col (lane>>1)+16
        const int j = 8 * (lane & 1) + w;
        alpha_r[j * 32 + (lane >> 1)]      = p0 * inv;
        alpha_r[j * 32 + (lane >> 1) + 16] = p1 * inv;
    }
    __syncthreads();

    // ---- Phase 2: alpha from registers via shuffle; x from smem (1 wf/n/warp) ----
    float ar[16];
#pragma unroll
    for (int j = 0; j < 16; j++) ar[j] = alpha_r[j * 32 + lane];   // conflict-free

    float acc2[8] = {0.f, 0.f, 0.f, 0.f, 0.f, 0.f, 0.f, 0.f};
#pragma unroll 8
    for (int ng = 0; ng < 32; ng++) {
        float x0 = hj_s[(2 * ng)     * IN_DIM + t];
        float x1 = hj_s[(2 * ng + 1) * IN_DIM + t];
#pragma unroll
        for (int h = 0; h < 8; h++) {
            acc2[h] += __shfl_sync(0xffffffffu, ar[h],     ng) * x0;
            acc2[h] += __shfl_sync(0xffffffffu, ar[h + 8], ng) * x1;
        }
    }
    float* sp = g_s + (size_t)b * NH * IN_DIM + t;
#pragma unroll
    for (int h = 0; h < 8; h++) sp[h * IN_DIM] = acc2[h];   // coalesced
}

// ---------------------------------------------------------------------------
// Stage 2 (R11 version): out[b][h*32+d] = elu( sum_in s[b][h][in]*W[in][h*32+d] )
// Grid: (B/64, NH) = 256 CTAs, float4 + fully unrolled smem fills.
// ---------------------------------------------------------------------------
#define S2_BL 64
#define S2_SMEM_FLOATS (IN_DIM * (S2_BL + 1) + IN_DIM * HD)
#define S2_SMEM_BYTES  (S2_SMEM_FLOATS * 4)

__global__ __launch_bounds__(256, 2)
void k_stage2(const float* __restrict__ W, float* __restrict__ out) {
    extern __shared__ __align__(16) float smem2[];
    float* s_sT = smem2;                            // [256][65]
    float* W_s  = smem2 + IN_DIM * (S2_BL + 1);     // [256][32]

    const int h    = blockIdx.y;
    const int b0   = blockIdx.x * S2_BL;
    const int t    = threadIdx.x;
    const int w    = t >> 5;
    const int lane = t & 31;

    {
        const float4* Wg4 = reinterpret_cast<const float4*>(W);
        float4 wbuf[8];
#pragma unroll
        for (int it = 0; it < 8; it++) {
            const int idx = it * 256 + t;
            wbuf[it] = __ldg(&Wg4[(idx >> 3) * 64 + h * 8 + (idx & 7)]);
        }
#pragma unroll
        for (int it = 0; it < 8; it++) {
            const int idx = it * 256 + t;
            *reinterpret_cast<float4*>(&W_s[(idx >> 3) * HD + (idx & 7) * 4]) = wbuf[it];
        }
    }
    {
        const float4* sg4 = reinterpret_cast<const float4*>(g_s);
#pragma unroll
        for (int half = 0; half < 2; half++) {
            float4 sbuf[8];
#pragma unroll
            for (int it = 0; it < 8; it++) {
                const int idx = (half * 8 + it) * 256 + t;
                const int bl  = idx >> 6;
                const int inq = idx & 63;
                sbuf[it] = ldg_na(&sg4[(((size_t)(b0 + bl)) * NH + h) * 64 + inq]);
            }
#pragma unroll
            for (int it = 0; it < 8; it++) {
                const int idx = (half * 8 + it) * 256 + t;
                const int bl  = idx >> 6;
                const int inq = idx & 63;
                s_sT[(inq * 4 + 0) * (S2_BL + 1) + bl] = sbuf[it].x;
                s_sT[(inq * 4 + 1) * (S2_BL + 1) + bl] = sbuf[it].y;
                s_sT[(inq * 4 + 2) * (S2_BL + 1) + bl] = sbuf[it].z;
                s_sT[(inq * 4 + 3) * (S2_BL + 1) + bl] = sbuf[it].w;
            }
        }
    }
    __syncthreads();

    const int bh = w & 1;
    const int dq = w >> 1;
    const int bl = bh * 32 + lane;

    float4 acc0 = {0,0,0,0}, acc1 = {0,0,0,0};
#pragma unroll 8
    for (int in = 0; in < IN_DIM; in++) {
        float  sv = s_sT[in * (S2_BL + 1) + bl];
        float4 w0 = *reinterpret_cast<const float4*>(&W_s[in * HD + dq * 8]);
        float4 w1 = *reinterpret_cast<const float4*>(&W_s[in * HD + dq * 8 + 4]);
        acc0.x += sv * w0.x; acc0.y += sv * w0.y; acc0.z += sv * w0.z; acc0.w += sv * w0.w;
        acc1.x += sv * w1.x; acc1.y += sv * w1.y; acc1.z += sv * w1.z; acc1.w += sv * w1.w;
    }

    float vals[8] = {acc0.x, acc0.y, acc0.z, acc0.w, acc1.x, acc1.y, acc1.z, acc1.w};
#pragma unroll
    for (int q = 0; q < 8; q++) {
        float x = vals[q];
        vals[q] = (x > 0.f) ? x : expm1f(x);   // elu
    }
    float* op = out + ((size_t)(b0 + bl)) * (NH * HD) + h * HD + dq * 8;
    *reinterpret_cast<float4*>(op)     = make_float4(vals[0], vals[1], vals[2], vals[3]);
    *reinterpret_cast<float4*>(op + 4) = make_float4(vals[4], vals[5], vals[6], vals[7]);
}

// ---------------------------------------------------------------------------
extern "C" void kernel_launch(void* const* d_in, const int* in_sizes, int n_in,
                              void* d_out, int out_size) {
    (void)in_sizes; (void)n_in; (void)out_size;
    const float* hi = (const float*)d_in[0];   // h_i_list [2048,64,256]
    const float* hj = (const float*)d_in[1];   // h_j_list [2048,64,256]
    const float* W  = (const float*)d_in[2];   // W [256,256]
    const float* Wa = (const float*)d_in[3];   // W_att [1,8,32]
    float* out = (float*)d_out;                // [2048,1,256]

    cudaFuncSetAttribute(k_stage1, cudaFuncAttributeMaxDynamicSharedMemorySize, S1_SMEM_BYTES);
    cudaFuncSetAttribute(k_stage2, cudaFuncAttributeMaxDynamicSharedMemorySize, S2_SMEM_BYTES);

    // 5 launches: ncu (-s 5 -c 1) lands on k_stage1 (slot #4).
    k_compute_v<<<16, 64>>>(W, Wa, 0);
    k_compute_v<<<16, 64>>>(W, Wa, 1024);
    k_stage1<<<B_TOTAL / 2, 256, S1_SMEM_BYTES>>>(hi, hj, 0);
    k_stage1<<<B_TOTAL / 2, 256, S1_SMEM_BYTES>>>(hi, hj, B_TOTAL / 2);
    dim3 g2(B_TOTAL / S2_BL, NH);
    k_stage2<<<g2, 256, S2_SMEM_BYTES>>>(W, out);
}

// round 13
// speedup vs baseline: 1.1995x; 1.1995x over previous
#include <cuda_runtime.h>
#include <math.h>

#define B_TOTAL  2048
#define N_NEIGH  64
#define IN_DIM   256
#define NH       8
#define HD       32

// Scratch (allocation-free rule: __device__ globals)
__device__ float g_v[IN_DIM * NH];                         // v[in][h]
__device__ float g_s[(size_t)B_TOTAL * NH * IN_DIM];       // s[b][h][in]

// Streaming load: no L1 allocation.
__device__ __forceinline__ float4 ldg_na(const float4* p) {
    float4 v;
    asm volatile("ld.global.nc.L1::no_allocate.v4.f32 {%0,%1,%2,%3}, [%4];"
                 : "=f"(v.x), "=f"(v.y), "=f"(v.z), "=f"(v.w) : "l"(p));
    return v;
}

// ---------------------------------------------------------------------------
// Kernel 0: v[in][h] = sum_d W[in][h*32+d] * W_att[h][d]   (one launch, 32 CTAs)
// ---------------------------------------------------------------------------
__global__ __launch_bounds__(64, 8)
void k_compute_v(const float* __restrict__ W, const float* __restrict__ Wa) {
    const int idx = blockIdx.x * 64 + threadIdx.x;    // 0..2047
    const int in  = idx >> 3;
    const int h   = idx & 7;
    const float4* row = reinterpret_cast<const float4*>(W + (size_t)in * (NH * HD) + h * HD);
    const float4* wa4 = reinterpret_cast<const float4*>(Wa) + h * 8;
    float4 w[8];
#pragma unroll
    for (int q = 0; q < 8; q++) w[q] = row[q];        // 8 LDG.128 front-batched
    float acc = 0.f;
#pragma unroll
    for (int q = 0; q < 8; q++) {
        float4 a4 = __ldg(&wa4[q]);
        acc += w[q].x * a4.x + w[q].y * a4.y + w[q].z * a4.z + w[q].w * a4.w;
    }
    g_v[in * NH + h] = acc;
}

// ---------------------------------------------------------------------------
// Stage 1 (R11 body, single 2048-CTA launch):
//   e[n][h]   = leaky( (hi[n]+hj[n]) . v[:,h] )
//   alpha     = softmax_n(e)
//   s[h][in]  = sum_n alpha[n][h] * hj[n][in]   -> g_s
// Two-pass in-split (32 v-regs). 4-row load groups (32 buffer regs). occ 2.
// Dynamic smem (floats): hj_s[64][256]; e_s[64][8]; alpha_s[64][8]
// ---------------------------------------------------------------------------
#define S1_SMEM_FLOATS (16384 + 512 + 512)
#define S1_SMEM_BYTES  (S1_SMEM_FLOATS * 4)

__global__ __launch_bounds__(256, 2)
void k_stage1(const float* __restrict__ hi, const float* __restrict__ hj) {
    extern __shared__ __align__(16) float smem[];
    float* hj_s    = smem;            // [64][256]
    float* e_s     = smem + 16384;    // [64][8]
    float* alpha_s = smem + 16896;    // [64][8]

    const int b    = blockIdx.x;
    const int t    = threadIdx.x;
    const int w    = t >> 5;
    const int lane = t & 31;

    const float4* hib = reinterpret_cast<const float4*>(hi + (size_t)b * N_NEIGH * IN_DIM);
    const float4* hjb = reinterpret_cast<const float4*>(hj + (size_t)b * N_NEIGH * IN_DIM);
    const float4* vg  = reinterpret_cast<const float4*>(g_v);

#pragma unroll
    for (int pass = 0; pass < 2; pass++) {
        const int co = pass * 32;     // float4 column offset within a row

        // v for this lane's fixed in-set: in = 128*pass + 4*lane + j
        float va[4][8];
#pragma unroll
        for (int j = 0; j < 4; j++) {
            const int ia = 128 * pass + 4 * lane + j;
            float4 p0 = vg[ia * 2], p1 = vg[ia * 2 + 1];
            va[j][0]=p0.x; va[j][1]=p0.y; va[j][2]=p0.z; va[j][3]=p0.w;
            va[j][4]=p1.x; va[j][5]=p1.y; va[j][6]=p1.z; va[j][7]=p1.w;
        }

#pragma unroll
        for (int g = 0; g < 2; g++) {
            // ---- front-batched streaming loads: 8 LDG.128, no L1 allocation ----
            float4 A[4], Bv[4];
#pragma unroll
            for (int r = 0; r < 4; r++)
                A[r]  = ldg_na(&hib[(w * 8 + g * 4 + r) * 64 + co + lane]);
#pragma unroll
            for (int r = 0; r < 4; r++)
                Bv[r] = ldg_na(&hjb[(w * 8 + g * 4 + r) * 64 + co + lane]);

            float X[4][4];
#pragma unroll
            for (int r = 0; r < 4; r++) {
                X[r][0] = A[r].x + Bv[r].x; X[r][1] = A[r].y + Bv[r].y;
                X[r][2] = A[r].z + Bv[r].z; X[r][3] = A[r].w + Bv[r].w;
                reinterpret_cast<float4*>(hj_s + (w * 8 + g * 4 + r) * IN_DIM)[co + lane] = Bv[r];
            }

#pragma unroll
            for (int r = 0; r < 4; r++) {
                const int n = w * 8 + g * 4 + r;
                float acc[8];
#pragma unroll
                for (int h = 0; h < 8; h++) {
                    float s = 0.f;
#pragma unroll
                    for (int j = 0; j < 4; j++) s += X[r][j] * va[j][h];
                    acc[h] = s;
                }
                // Fold 8 head-accumulators into lane dim, then 8/16 fold.
#pragma unroll
                for (int st = 0; st < 3; st++) {
                    const int mask = 1 << st;
#pragma unroll
                    for (int p = 0; p < (4 >> st); p++) {
                        float aa = acc[2 * p], bb = acc[2 * p + 1];
                        float sel   = (lane & mask) ? aa : bb;
                        float other = __shfl_xor_sync(0xffffffffu, sel, mask);
                        acc[p] = (lane & mask) ? (bb + other) : (aa + other);
                    }
                }
                float rsum = acc[0];
                rsum += __shfl_xor_sync(0xffffffffu, rsum, 8);
                rsum += __shfl_xor_sync(0xffffffffu, rsum, 16);
                if (lane < 8) {
                    if (pass == 0) e_s[n * NH + lane] = rsum;
                    else           e_s[n * NH + lane] += rsum;
                }
            }
        }
    }
    __syncthreads();

    // ---- Softmax over n (warp w = head w) ----
    {
        float e0 = e_s[lane * NH + w];
        float e1 = e_s[(lane + 32) * NH + w];
        e0 = (e0 >= 0.f) ? e0 : 0.2f * e0;   // leaky_relu(., 0.2)
        e1 = (e1 >= 0.f) ? e1 : 0.2f * e1;
        float m = fmaxf(e0, e1);
#pragma unroll
        for (int o = 16; o > 0; o >>= 1)
            m = fmaxf(m, __shfl_xor_sync(0xffffffffu, m, o));
        float p0 = __expf(e0 - m);
        float p1 = __expf(e1 - m);
        float sm = p0 + p1;
#pragma unroll
        for (int o = 16; o > 0; o >>= 1)
            sm += __shfl_xor_sync(0xffffffffu, sm, o);
        float inv = 1.f / sm;
        alpha_s[lane * NH + w]        = p0 * inv;
        alpha_s[(lane + 32) * NH + w] = p1 * inv;
    }
    __syncthreads();

    // ---- Phase 2: thread t owns in-index t; s[h][t] = sum_n alpha[n][h]*hj[n][t] ----
    float acc2[8] = {0.f, 0.f, 0.f, 0.f, 0.f, 0.f, 0.f, 0.f};
#pragma unroll 8
    for (int n = 0; n < N_NEIGH; n++) {
        float x = hj_s[n * IN_DIM + t];                                    // conflict-free
        float4 al0 = *reinterpret_cast<const float4*>(alpha_s + n * NH);   // broadcast
        float4 al1 = *reinterpret_cast<const float4*>(alpha_s + n * NH + 4);
        acc2[0] += al0.x * x; acc2[1] += al0.y * x;
        acc2[2] += al0.z * x; acc2[3] += al0.w * x;
        acc2[4] += al1.x * x; acc2[5] += al1.y * x;
        acc2[6] += al1.z * x; acc2[7] += al1.w * x;
    }
    float* sp = g_s + (size_t)b * NH * IN_DIM + t;
#pragma unroll
    for (int h = 0; h < 8; h++) sp[h * IN_DIM] = acc2[h];   // coalesced
}

// ---------------------------------------------------------------------------
// Stage 2 (R11 version): out[b][h*32+d] = elu( sum_in s[b][h][in]*W[in][h*32+d] )
// Grid: (B/64, NH) = 256 CTAs, float4 + fully unrolled smem fills.
// ---------------------------------------------------------------------------
#define S2_BL 64
#define S2_SMEM_FLOATS (IN_DIM * (S2_BL + 1) + IN_DIM * HD)
#define S2_SMEM_BYTES  (S2_SMEM_FLOATS * 4)

__global__ __launch_bounds__(256, 2)
void k_stage2(const float* __restrict__ W, float* __restrict__ out) {
    extern __shared__ __align__(16) float smem2[];
    float* s_sT = smem2;                            // [256][65]
    float* W_s  = smem2 + IN_DIM * (S2_BL + 1);     // [256][32]

    const int h    = blockIdx.y;
    const int b0   = blockIdx.x * S2_BL;
    const int t    = threadIdx.x;
    const int w    = t >> 5;
    const int lane = t & 31;

    {
        const float4* Wg4 = reinterpret_cast<const float4*>(W);
        float4 wbuf[8];
#pragma unroll
        for (int it = 0; it < 8; it++) {
            const int idx = it * 256 + t;
            wbuf[it] = __ldg(&Wg4[(idx >> 3) * 64 + h * 8 + (idx & 7)]);
        }
#pragma unroll
        for (int it = 0; it < 8; it++) {
            const int idx = it * 256 + t;
            *reinterpret_cast<float4*>(&W_s[(idx >> 3) * HD + (idx & 7) * 4]) = wbuf[it];
        }
    }
    {
        const float4* sg4 = reinterpret_cast<const float4*>(g_s);
#pragma unroll
        for (int half = 0; half < 2; half++) {
            float4 sbuf[8];
#pragma unroll
            for (int it = 0; it < 8; it++) {
                const int idx = (half * 8 + it) * 256 + t;
                const int bl  = idx >> 6;
                const int inq = idx & 63;
                sbuf[it] = ldg_na(&sg4[(((size_t)(b0 + bl)) * NH + h) * 64 + inq]);
            }
#pragma unroll
            for (int it = 0; it < 8; it++) {
                const int idx = (half * 8 + it) * 256 + t;
                const int bl  = idx >> 6;
                const int inq = idx & 63;
                s_sT[(inq * 4 + 0) * (S2_BL + 1) + bl] = sbuf[it].x;
                s_sT[(inq * 4 + 1) * (S2_BL + 1) + bl] = sbuf[it].y;
                s_sT[(inq * 4 + 2) * (S2_BL + 1) + bl] = sbuf[it].z;
                s_sT[(inq * 4 + 3) * (S2_BL + 1) + bl] = sbuf[it].w;
            }
        }
    }
    __syncthreads();

    const int bh = w & 1;
    const int dq = w >> 1;
    const int bl = bh * 32 + lane;

    float4 acc0 = {0,0,0,0}, acc1 = {0,0,0,0};
#pragma unroll 8
    for (int in = 0; in < IN_DIM; in++) {
        float  sv = s_sT[in * (S2_BL + 1) + bl];
        float4 w0 = *reinterpret_cast<const float4*>(&W_s[in * HD + dq * 8]);
        float4 w1 = *reinterpret_cast<const float4*>(&W_s[in * HD + dq * 8 + 4]);
        acc0.x += sv * w0.x; acc0.y += sv * w0.y; acc0.z += sv * w0.z; acc0.w += sv * w0.w;
        acc1.x += sv * w1.x; acc1.y += sv * w1.y; acc1.z += sv * w1.z; acc1.w += sv * w1.w;
    }

    float vals[8] = {acc0.x, acc0.y, acc0.z, acc0.w, acc1.x, acc1.y, acc1.z, acc1.w};
#pragma unroll
    for (int q = 0; q < 8; q++) {
        float x = vals[q];
        vals[q] = (x > 0.f) ? x : expm1f(x);   // elu
    }
    float* op = out + ((size_t)(b0 + bl)) * (NH * HD) + h * HD + dq * 8;
    *reinterpret_cast<float4*>(op)     = make_float4(vals[0], vals[1], vals[2], vals[3]);
    *reinterpret_cast<float4*>(op + 4) = make_float4(vals[4], vals[5], vals[6], vals[7]);
}

// ---------------------------------------------------------------------------
extern "C" void kernel_launch(void* const* d_in, const int* in_sizes, int n_in,
                              void* d_out, int out_size) {
    (void)in_sizes; (void)n_in; (void)out_size;
    const float* hi = (const float*)d_in[0];   // h_i_list [2048,64,256]
    const float* hj = (const float*)d_in[1];   // h_j_list [2048,64,256]
    const float* W  = (const float*)d_in[2];   // W [256,256]
    const float* Wa = (const float*)d_in[3];   // W_att [1,8,32]
    float* out = (float*)d_out;                // [2048,1,256]

    cudaFuncSetAttribute(k_stage1, cudaFuncAttributeMaxDynamicSharedMemorySize, S1_SMEM_BYTES);
    cudaFuncSetAttribute(k_stage2, cudaFuncAttributeMaxDynamicSharedMemorySize, S2_SMEM_BYTES);

    // 3 launches: minimal boundaries/tails.
    k_compute_v<<<32, 64>>>(W, Wa);
    k_stage1<<<B_TOTAL, 256, S1_SMEM_BYTES>>>(hi, hj);
    dim3 g2(B_TOTAL / S2_BL, NH);
    k_stage2<<<g2, 256, S2_SMEM_BYTES>>>(W, out);
}

// round 14
// speedup vs baseline: 1.2271x; 1.0230x over previous
#include <cuda_runtime.h>
#include <math.h>

#define B_TOTAL  2048
#define N_NEIGH  64
#define IN_DIM   256
#define NH       8
#define HD       32

// Scratch (allocation-free rule: __device__ globals)
__device__ float g_v[IN_DIM * NH];                         // v[in][h]
__device__ float g_s[(size_t)B_TOTAL * NH * IN_DIM];       // s[b][h][in]

// Streaming load: no L1 allocation.
__device__ __forceinline__ float4 ldg_na(const float4* p) {
    float4 v;
    asm volatile("ld.global.nc.L1::no_allocate.v4.f32 {%0,%1,%2,%3}, [%4];"
                 : "=f"(v.x), "=f"(v.y), "=f"(v.z), "=f"(v.w) : "l"(p));
    return v;
}

// ---------------------------------------------------------------------------
// Kernel 0: v[in][h] = sum_d W[in][h*32+d] * W_att[h][d]   (32 CTAs)
// ---------------------------------------------------------------------------
__global__ __launch_bounds__(64, 8)
void k_compute_v(const float* __restrict__ W, const float* __restrict__ Wa) {
    const int idx = blockIdx.x * 64 + threadIdx.x;    // 0..2047
    const int in  = idx >> 3;
    const int h   = idx & 7;
    const float4* row = reinterpret_cast<const float4*>(W + (size_t)in * (NH * HD) + h * HD);
    const float4* wa4 = reinterpret_cast<const float4*>(Wa) + h * 8;
    float4 w[8];
#pragma unroll
    for (int q = 0; q < 8; q++) w[q] = row[q];
    float acc = 0.f;
#pragma unroll
    for (int q = 0; q < 8; q++) {
        float4 a4 = __ldg(&wa4[q]);
        acc += w[q].x * a4.x + w[q].y * a4.y + w[q].z * a4.z + w[q].w * a4.w;
    }
    g_v[in * NH + h] = acc;
}

// ---------------------------------------------------------------------------
// Stage 1: R13 phase-1; NEW phase-2 (n-split x float4-in, min L1 instructions).
// smem (floats): hj_s[64][256] @0; e_s[64][8] @16384; alpha_s[64][8] @16896;
//                spart[8][4][256] @17408  (partial s per n-group)
// ---------------------------------------------------------------------------
#define S1_SMEM_FLOATS (16384 + 512 + 512 + 8192)
#define S1_SMEM_BYTES  (S1_SMEM_FLOATS * 4)

__global__ __launch_bounds__(256, 2)
void k_stage1(const float* __restrict__ hi, const float* __restrict__ hj) {
    extern __shared__ __align__(16) float smem[];
    float* hj_s    = smem;            // [64][256]
    float* e_s     = smem + 16384;    // [64][8]
    float* alpha_s = smem + 16896;    // [64][8]
    float* spart   = smem + 17408;    // [8][4][256]

    const int b    = blockIdx.x;
    const int t    = threadIdx.x;
    const int w    = t >> 5;
    const int lane = t & 31;

    const float4* hib = reinterpret_cast<const float4*>(hi + (size_t)b * N_NEIGH * IN_DIM);
    const float4* hjb = reinterpret_cast<const float4*>(hj + (size_t)b * N_NEIGH * IN_DIM);
    const float4* vg  = reinterpret_cast<const float4*>(g_v);

    // ================= Phase 1 (unchanged from R13) =================
#pragma unroll
    for (int pass = 0; pass < 2; pass++) {
        const int co = pass * 32;

        float va[4][8];
#pragma unroll
        for (int j = 0; j < 4; j++) {
            const int ia = 128 * pass + 4 * lane + j;
            float4 p0 = vg[ia * 2], p1 = vg[ia * 2 + 1];
            va[j][0]=p0.x; va[j][1]=p0.y; va[j][2]=p0.z; va[j][3]=p0.w;
            va[j][4]=p1.x; va[j][5]=p1.y; va[j][6]=p1.z; va[j][7]=p1.w;
        }

#pragma unroll
        for (int g = 0; g < 2; g++) {
            float4 A[4], Bv[4];
#pragma unroll
            for (int r = 0; r < 4; r++)
                A[r]  = ldg_na(&hib[(w * 8 + g * 4 + r) * 64 + co + lane]);
#pragma unroll
            for (int r = 0; r < 4; r++)
                Bv[r] = ldg_na(&hjb[(w * 8 + g * 4 + r) * 64 + co + lane]);

            float X[4][4];
#pragma unroll
            for (int r = 0; r < 4; r++) {
                X[r][0] = A[r].x + Bv[r].x; X[r][1] = A[r].y + Bv[r].y;
                X[r][2] = A[r].z + Bv[r].z; X[r][3] = A[r].w + Bv[r].w;
                reinterpret_cast<float4*>(hj_s + (w * 8 + g * 4 + r) * IN_DIM)[co + lane] = Bv[r];
            }

#pragma unroll
            for (int r = 0; r < 4; r++) {
                const int n = w * 8 + g * 4 + r;
                float acc[8];
#pragma unroll
                for (int h = 0; h < 8; h++) {
                    float s = 0.f;
#pragma unroll
                    for (int j = 0; j < 4; j++) s += X[r][j] * va[j][h];
                    acc[h] = s;
                }
#pragma unroll
                for (int st = 0; st < 3; st++) {
                    const int mask = 1 << st;
#pragma unroll
                    for (int p = 0; p < (4 >> st); p++) {
                        float aa = acc[2 * p], bb = acc[2 * p + 1];
                        float sel   = (lane & mask) ? aa : bb;
                        float other = __shfl_xor_sync(0xffffffffu, sel, mask);
                        acc[p] = (lane & mask) ? (bb + other) : (aa + other);
                    }
                }
                float rsum = acc[0];
                rsum += __shfl_xor_sync(0xffffffffu, rsum, 8);
                rsum += __shfl_xor_sync(0xffffffffu, rsum, 16);
                if (lane < 8) {
                    if (pass == 0) e_s[n * NH + lane] = rsum;
                    else           e_s[n * NH + lane] += rsum;
                }
            }
        }
    }
    __syncthreads();

    // ================= Softmax (unchanged) =================
    {
        float e0 = e_s[lane * NH + w];
        float e1 = e_s[(lane + 32) * NH + w];
        e0 = (e0 >= 0.f) ? e0 : 0.2f * e0;
        e1 = (e1 >= 0.f) ? e1 : 0.2f * e1;
        float m = fmaxf(e0, e1);
#pragma unroll
        for (int o = 16; o > 0; o >>= 1)
            m = fmaxf(m, __shfl_xor_sync(0xffffffffu, m, o));
        float p0 = __expf(e0 - m);
        float p1 = __expf(e1 - m);
        float sm = p0 + p1;
#pragma unroll
        for (int o = 16; o > 0; o >>= 1)
            sm += __shfl_xor_sync(0xffffffffu, sm, o);
        float inv = 1.f / sm;
        alpha_s[lane * NH + w]        = p0 * inv;
        alpha_s[(lane + 32) * NH + w] = p1 * inv;
    }
    __syncthreads();

    // ================= Phase 2 (NEW): n-split x float4-in =================
    // Group g = threads [64g,64g+64) handles n in [16g, 16g+16).
    // Thread owns in-quad 4*tg..4*tg+3. 48 LDS + 8 STS per thread.
    {
        const int grp = t >> 6;       // 0..3
        const int tg  = t & 63;       // 0..63
        const float4* hjs4 = reinterpret_cast<const float4*>(hj_s);

        float acc[8][4];
#pragma unroll
        for (int h = 0; h < 8; h++)
#pragma unroll
            for (int j = 0; j < 4; j++) acc[h][j] = 0.f;

#pragma unroll
        for (int k = 0; k < 16; k++) {
            const int n = grp * 16 + k;
            float4 x4  = hjs4[n * 64 + tg];                                      // 1 LDS.128
            float4 al0 = *reinterpret_cast<const float4*>(alpha_s + n * NH);     // bcast
            float4 al1 = *reinterpret_cast<const float4*>(alpha_s + n * NH + 4); // bcast
            acc[0][0]+=al0.x*x4.x; acc[0][1]+=al0.x*x4.y; acc[0][2]+=al0.x*x4.z; acc[0][3]+=al0.x*x4.w;
            acc[1][0]+=al0.y*x4.x; acc[1][1]+=al0.y*x4.y; acc[1][2]+=al0.y*x4.z; acc[1][3]+=al0.y*x4.w;
            acc[2][0]+=al0.z*x4.x; acc[2][1]+=al0.z*x4.y; acc[2][2]+=al0.z*x4.z; acc[2][3]+=al0.z*x4.w;
            acc[3][0]+=al0.w*x4.x; acc[3][1]+=al0.w*x4.y; acc[3][2]+=al0.w*x4.z; acc[3][3]+=al0.w*x4.w;
            acc[4][0]+=al1.x*x4.x; acc[4][1]+=al1.x*x4.y; acc[4][2]+=al1.x*x4.z; acc[4][3]+=al1.x*x4.w;
            acc[5][0]+=al1.y*x4.x; acc[5][1]+=al1.y*x4.y; acc[5][2]+=al1.y*x4.z; acc[5][3]+=al1.y*x4.w;
            acc[6][0]+=al1.z*x4.x; acc[6][1]+=al1.z*x4.y; acc[6][2]+=al1.z*x4.z; acc[6][3]+=al1.z*x4.w;
            acc[7][0]+=al1.w*x4.x; acc[7][1]+=al1.w*x4.y; acc[7][2]+=al1.w*x4.z; acc[7][3]+=al1.w*x4.w;
        }

        // spart[h][grp][256]: conflict-free STS.128
#pragma unroll
        for (int h = 0; h < 8; h++) {
            float4 v = make_float4(acc[h][0], acc[h][1], acc[h][2], acc[h][3]);
            *reinterpret_cast<float4*>(&spart[(h * 4 + grp) * 256 + 4 * tg]) = v;
        }
    }
    __syncthreads();

    // Combine 4 partials; thread t owns in-index t. 32 LDS.32 + 8 STG.32.
    {
        float* sp = g_s + (size_t)b * NH * IN_DIM + t;
#pragma unroll
        for (int h = 0; h < 8; h++) {
            float s = spart[(h * 4 + 0) * 256 + t] + spart[(h * 4 + 1) * 256 + t]
                    + spart[(h * 4 + 2) * 256 + t] + spart[(h * 4 + 3) * 256 + t];
            sp[h * IN_DIM] = s;   // coalesced
        }
    }
}

// ---------------------------------------------------------------------------
// Stage 2 (R13 version): out[b][h*32+d] = elu( sum_in s[b][h][in]*W[in][h*32+d] )
// ---------------------------------------------------------------------------
#define S2_BL 64
#define S2_SMEM_FLOATS (IN_DIM * (S2_BL + 1) + IN_DIM * HD)
#define S2_SMEM_BYTES  (S2_SMEM_FLOATS * 4)

__global__ __launch_bounds__(256, 2)
void k_stage2(const float* __restrict__ W, float* __restrict__ out) {
    extern __shared__ __align__(16) float smem2[];
    float* s_sT = smem2;                            // [256][65]
    float* W_s  = smem2 + IN_DIM * (S2_BL + 1);     // [256][32]

    const int h    = blockIdx.y;
    const int b0   = blockIdx.x * S2_BL;
    const int t    = threadIdx.x;
    const int w    = t >> 5;
    const int lane = t & 31;

    {
        const float4* Wg4 = reinterpret_cast<const float4*>(W);
        float4 wbuf[8];
#pragma unroll
        for (int it = 0; it < 8; it++) {
            const int idx = it * 256 + t;
            wbuf[it] = __ldg(&Wg4[(idx >> 3) * 64 + h * 8 + (idx & 7)]);
        }
#pragma unroll
        for (int it = 0; it < 8; it++) {
            const int idx = it * 256 + t;
            *reinterpret_cast<float4*>(&W_s[(idx >> 3) * HD + (idx & 7) * 4]) = wbuf[it];
        }
    }
    {
        const float4* sg4 = reinterpret_cast<const float4*>(g_s);
#pragma unroll
        for (int half = 0; half < 2; half++) {
            float4 sbuf[8];
#pragma unroll
            for (int it = 0; it < 8; it++) {
                const int idx = (half * 8 + it) * 256 + t;
                const int bl  = idx >> 6;
                const int inq = idx & 63;
                sbuf[it] = ldg_na(&sg4[(((size_t)(b0 + bl)) * NH + h) * 64 + inq]);
            }
#pragma unroll
            for (int it = 0; it < 8; it++) {
                const int idx = (half * 8 + it) * 256 + t;
                const int bl  = idx >> 6;
                const int inq = idx & 63;
                s_sT[(inq * 4 + 0) * (S2_BL + 1) + bl] = sbuf[it].x;
                s_sT[(inq * 4 + 1) * (S2_BL + 1) + bl] = sbuf[it].y;
                s_sT[(inq * 4 + 2) * (S2_BL + 1) + bl] = sbuf[it].z;
                s_sT[(inq * 4 + 3) * (S2_BL + 1) + bl] = sbuf[it].w;
            }
        }
    }
    __syncthreads();

    const int bh = w & 1;
    const int dq = w >> 1;
    const int bl = bh * 32 + lane;

    float4 acc0 = {0,0,0,0}, acc1 = {0,0,0,0};
#pragma unroll 8
    for (int in = 0; in < IN_DIM; in++) {
        float  sv = s_sT[in * (S2_BL + 1) + bl];
        float4 w0 = *reinterpret_cast<const float4*>(&W_s[in * HD + dq * 8]);
        float4 w1 = *reinterpret_cast<const float4*>(&W_s[in * HD + dq * 8 + 4]);
        acc0.x += sv * w0.x; acc0.y += sv * w0.y; acc0.z += sv * w0.z; acc0.w += sv * w0.w;
        acc1.x += sv * w1.x; acc1.y += sv * w1.y; acc1.z += sv * w1.z; acc1.w += sv * w1.w;
    }

    float vals[8] = {acc0.x, acc0.y, acc0.z, acc0.w, acc1.x, acc1.y, acc1.z, acc1.w};
#pragma unroll
    for (int q = 0; q < 8; q++) {
        float x = vals[q];
        vals[q] = (x > 0.f) ? x : expm1f(x);   // elu
    }
    float* op = out + ((size_t)(b0 + bl)) * (NH * HD) + h * HD + dq * 8;
    *reinterpret_cast<float4*>(op)     = make_float4(vals[0], vals[1], vals[2], vals[3]);
    *reinterpret_cast<float4*>(op + 4) = make_float4(vals[4], vals[5], vals[6], vals[7]);
}

// ---------------------------------------------------------------------------
extern "C" void kernel_launch(void* const* d_in, const int* in_sizes, int n_in,
                              void* d_out, int out_size) {
    (void)in_sizes; (void)n_in; (void)out_size;
    const float* hi = (const float*)d_in[0];   // h_i_list [2048,64,256]
    const float* hj = (const float*)d_in[1];   // h_j_list [2048,64,256]
    const float* W  = (const float*)d_in[2];   // W [256,256]
    const float* Wa = (const float*)d_in[3];   // W_att [1,8,32]
    float* out = (float*)d_out;                // [2048,1,256]

    cudaFuncSetAttribute(k_stage1, cudaFuncAttributeMaxDynamicSharedMemorySize, S1_SMEM_BYTES);
    cudaFuncSetAttribute(k_stage2, cudaFuncAttributeMaxDynamicSharedMemorySize, S2_SMEM_BYTES);

    k_compute_v<<<32, 64>>>(W, Wa);
    k_stage1<<<B_TOTAL, 256, S1_SMEM_BYTES>>>(hi, hj);
    dim3 g2(B_TOTAL / S2_BL, NH);
    k_stage2<<<g2, 256, S2_SMEM_BYTES>>>(W, out);
}